// round 10
// baseline (speedup 1.0000x reference)
#include <cuda_runtime.h>

// neigh_Conv: out[n,c,h,w] = b[c] + sum_{k<8} W[c,k] * x[n,c+k,h,w]
// x: (16, 200, 128, 128) f32 -> out: (16, 193, 128, 128) f32
//
// R10 = R9 (NCHUNK=4, 256-thr CTAs, cp.async consume-then-refill staging,
// diagonal zero-padded weights, 8-slot accumulator ring) with the stage
// ring widened 8 -> 16 slots (DEPTH=16, wait_group 15):
//   64KB stage smem/CTA -> still 3 CTAs/SM (reg limit was 3 anyway),
//   per-thread in-flight loads 8 -> 16 (~196KB/SM) to absorb DRAM jitter.

#define HW4    4096   // 128*128/4 float4 per plane
#define CIN    200
#define OUTC   193
#define NCHUNK 4
#define CHG    49     // output channels per chunk (last: 46)
#define LOOPN  64     // multiple of 16, >= max nin (=56)
#define DEPTH  16
#define BLK    256

__global__ __launch_bounds__(BLK)
void neigh_conv_kernel(const float* __restrict__ x,
                       const float* __restrict__ Wg,   // (193, 8) row-major
                       const float* __restrict__ b,
                       float4* __restrict__ out) {
    __shared__ float4 stg[DEPTH * BLK];    // [slot][tid], 64 KB
    __shared__ float4 sDW[LOOPN * 2];      // dW[c] = 8 floats (2 float4)
    __shared__ float  sB[LOOPN];

    const int t     = threadIdx.x;
    const int cbase = blockIdx.y * CHG;
    const int nout  = min(CHG, OUTC - cbase);   // 49 or 46
    const int nin   = nout + 7;

    // dW[c][k] = W[c-k][k] if 0 <= c-k < nout else 0  (c = 0..63)
    float* sDWf = (float*)sDW;
    for (int i = t; i < LOOPN * 8; i += BLK) {
        const int c = i >> 3, k = i & 7;
        const int oc = c - k;
        sDWf[i] = ((unsigned)oc < (unsigned)nout) ? Wg[(cbase + oc) * 8 + k] : 0.0f;
    }
    for (int i = t; i < LOOPN; i += BLK)
        sB[i] = (i < nout) ? b[cbase + i] : 0.0f;
    __syncthreads();

    const int gid = blockIdx.x * BLK + t;    // 0..65535
    const int n   = gid >> 12;
    const int pos = gid & 4095;

    const float4* xin = (const float4*)x + ((size_t)n * CIN  + cbase) * HW4 + pos;
    // Pre-offset by -7 planes so the emit address is op + c*HW4.
    float4*       op  = out + ((size_t)n * OUTC + (cbase - 7)) * HW4 + pos;

    const unsigned sbase = (unsigned)__cvta_generic_to_shared(&stg[t]);
    // slot s lives at sbase + s*(BLK*16) bytes

    // Prologue: planes 0..15 fill all 16 slots, one commit group each.
    // (nin >= 53 > 16, so all prologue planes are in range.)
#pragma unroll
    for (int p = 0; p < DEPTH; ++p) {
        const unsigned sa = sbase + p * (BLK * 16);
        const float4* ga = xin + (size_t)p * HW4;
        asm volatile("cp.async.cg.shared.global [%0], [%1], 16;\n"
                     :: "r"(sa), "l"(ga));
        asm volatile("cp.async.commit_group;\n" ::: "memory");
    }

    float4 acc[8];   // acc[oc & 7] accumulates output channel oc

    for (int cb = 0; cb < LOOPN; cb += DEPTH) {
#pragma unroll
        for (int u = 0; u < DEPTH; ++u) {
            const int c = cb + u;

            // Plane c is the oldest pending group (15 newer allowed).
            asm volatile("cp.async.wait_group 15;\n" ::: "memory");

            float4 xv;
            const unsigned sa = sbase + u * (BLK * 16);
            asm volatile("ld.shared.v4.f32 {%0,%1,%2,%3}, [%4];"
                         : "=f"(xv.x), "=f"(xv.y), "=f"(xv.z), "=f"(xv.w)
                         : "r"(sa));

            // Refill THIS slot with plane c+16 (fill lands >=234cyc after
            // the 29cyc LDS above -- no hazard).
            if (c + DEPTH < nin) {
                const float4* ga = xin + (size_t)(c + DEPTH) * HW4;
                asm volatile("cp.async.cg.shared.global [%0], [%1], 16;\n"
                             :: "r"(sa), "l"(ga));
            }
            asm volatile("cp.async.commit_group;\n" ::: "memory");

            const float4 w0 = sDW[c * 2];       // k = 0..3
            const float4 w1 = sDW[c * 2 + 1];   // k = 4..7
            const float  bb = sB[c];

            // k=7 completes output c-7 (acc slot (u+1)&7), then emit.
            {
                const int s = (u + 1) & 7;
                acc[s].x = fmaf(w1.w, xv.x, acc[s].x);
                acc[s].y = fmaf(w1.w, xv.y, acc[s].y);
                acc[s].z = fmaf(w1.w, xv.z, acc[s].z);
                acc[s].w = fmaf(w1.w, xv.w, acc[s].w);
                if ((unsigned)(c - 7) < (unsigned)nout)
                    __stcs(op + (size_t)c * HW4, acc[s]);
            }
            // k = 6..1 (weights zero outside valid range -> no guards).
            {
                const int s = (u + 2) & 7;
                acc[s].x = fmaf(w1.z, xv.x, acc[s].x);
                acc[s].y = fmaf(w1.z, xv.y, acc[s].y);
                acc[s].z = fmaf(w1.z, xv.z, acc[s].z);
                acc[s].w = fmaf(w1.z, xv.w, acc[s].w);
            }
            {
                const int s = (u + 3) & 7;
                acc[s].x = fmaf(w1.y, xv.x, acc[s].x);
                acc[s].y = fmaf(w1.y, xv.y, acc[s].y);
                acc[s].z = fmaf(w1.y, xv.z, acc[s].z);
                acc[s].w = fmaf(w1.y, xv.w, acc[s].w);
            }
            {
                const int s = (u + 4) & 7;
                acc[s].x = fmaf(w1.x, xv.x, acc[s].x);
                acc[s].y = fmaf(w1.x, xv.y, acc[s].y);
                acc[s].z = fmaf(w1.x, xv.z, acc[s].z);
                acc[s].w = fmaf(w1.x, xv.w, acc[s].w);
            }
            {
                const int s = (u + 5) & 7;
                acc[s].x = fmaf(w0.w, xv.x, acc[s].x);
                acc[s].y = fmaf(w0.w, xv.y, acc[s].y);
                acc[s].z = fmaf(w0.w, xv.z, acc[s].z);
                acc[s].w = fmaf(w0.w, xv.w, acc[s].w);
            }
            {
                const int s = (u + 6) & 7;
                acc[s].x = fmaf(w0.z, xv.x, acc[s].x);
                acc[s].y = fmaf(w0.z, xv.y, acc[s].y);
                acc[s].z = fmaf(w0.z, xv.z, acc[s].z);
                acc[s].w = fmaf(w0.z, xv.w, acc[s].w);
            }
            {
                const int s = (u + 7) & 7;
                acc[s].x = fmaf(w0.y, xv.x, acc[s].x);
                acc[s].y = fmaf(w0.y, xv.y, acc[s].y);
                acc[s].z = fmaf(w0.y, xv.z, acc[s].z);
                acc[s].w = fmaf(w0.y, xv.w, acc[s].w);
            }
            // k=0: (re)init acc slot u&7 for output c with bias + 1st term.
            {
                const int s = u & 7;
                acc[s].x = fmaf(w0.x, xv.x, bb);
                acc[s].y = fmaf(w0.x, xv.y, bb);
                acc[s].z = fmaf(w0.x, xv.z, bb);
                acc[s].w = fmaf(w0.x, xv.w, bb);
            }
        }
    }
}

extern "C" void kernel_launch(void* const* d_in, const int* in_sizes, int n_in,
                              void* d_out, int out_size) {
    const float* x  = (const float*)d_in[0];
    const float* Wg = (const float*)d_in[1];
    const float* b  = (const float*)d_in[2];
    float4* out = (float4*)d_out;

    dim3 grid(65536 / BLK, NCHUNK);
    neigh_conv_kernel<<<grid, BLK>>>(x, Wg, b, out);
}

// round 11
// speedup vs baseline: 1.0379x; 1.0379x over previous
#include <cuda_runtime.h>

// neigh_Conv: out[n,c,h,w] = b[c] + sum_{k<8} W[c,k] * x[n,c+k,h,w]
// x: (16, 200, 128, 128) f32 -> out: (16, 193, 128, 128) f32
//
// R11 = R9 core (256-thr CTAs, cp.async DEPTH=8 consume-then-refill,
// diagonal zero-padded weights, 8-slot accumulator ring) with NCHUNK 4->8:
// T_CTA ~26us -> ~13us to shrink the ragged wave tail (1024 CTAs / 444
// concurrent = 2.31 waves cost ~T_CTA/2 idle). Price: +6.7% traffic.

#define HW4    4096   // 128*128/4 float4 per plane
#define CIN    200
#define OUTC   193
#define NCHUNK 8
#define CHG    25     // output channels per chunk (last: 18)
#define LOOPN  32     // multiple of 8, >= max nin (=32)
#define DEPTH  8
#define BLK    256

__global__ __launch_bounds__(BLK)
void neigh_conv_kernel(const float* __restrict__ x,
                       const float* __restrict__ Wg,   // (193, 8) row-major
                       const float* __restrict__ b,
                       float4* __restrict__ out) {
    __shared__ float4 stg[DEPTH * BLK];    // [slot][tid], 32 KB
    __shared__ float4 sDW[LOOPN * 2];      // dW[c] = 8 floats (2 float4)
    __shared__ float  sB[LOOPN];

    const int t     = threadIdx.x;
    const int cbase = blockIdx.y * CHG;
    const int nout  = min(CHG, OUTC - cbase);   // 25 or 18
    const int nin   = nout + 7;                 // 32 or 25

    // dW[c][k] = W[c-k][k] if 0 <= c-k < nout else 0  (c = 0..31)
    float* sDWf = (float*)sDW;
    for (int i = t; i < LOOPN * 8; i += BLK) {
        const int c = i >> 3, k = i & 7;
        const int oc = c - k;
        sDWf[i] = ((unsigned)oc < (unsigned)nout) ? Wg[(cbase + oc) * 8 + k] : 0.0f;
    }
    if (t < LOOPN) sB[t] = (t < nout) ? b[cbase + t] : 0.0f;
    __syncthreads();

    const int gid = blockIdx.x * BLK + t;    // 0..65535
    const int n   = gid >> 12;
    const int pos = gid & 4095;

    const float4* xin = (const float4*)x + ((size_t)n * CIN  + cbase) * HW4 + pos;
    // Pre-offset by -7 planes so the emit address is op + c*HW4.
    float4*       op  = out + ((size_t)n * OUTC + (cbase - 7)) * HW4 + pos;

    const unsigned sbase = (unsigned)__cvta_generic_to_shared(&stg[t]);
    // slot s lives at sbase + s*(BLK*16) bytes

    // Prologue: planes 0..7 fill all 8 slots, one commit group each.
    // Guard: last chunk has nin=25 > 8, so all prologue planes valid.
#pragma unroll
    for (int p = 0; p < DEPTH; ++p) {
        const unsigned sa = sbase + p * (BLK * 16);
        const float4* ga = xin + (size_t)p * HW4;
        asm volatile("cp.async.cg.shared.global [%0], [%1], 16;\n"
                     :: "r"(sa), "l"(ga));
        asm volatile("cp.async.commit_group;\n" ::: "memory");
    }

    float4 acc[8];   // acc[oc & 7] accumulates output channel oc

    for (int cb = 0; cb < LOOPN; cb += 8) {
#pragma unroll
        for (int u = 0; u < 8; ++u) {
            const int c = cb + u;

            // Plane c is the oldest pending group (7 newer allowed).
            asm volatile("cp.async.wait_group 7;\n" ::: "memory");

            float4 xv;
            const unsigned sa = sbase + u * (BLK * 16);
            asm volatile("ld.shared.v4.f32 {%0,%1,%2,%3}, [%4];"
                         : "=f"(xv.x), "=f"(xv.y), "=f"(xv.z), "=f"(xv.w)
                         : "r"(sa));

            // Refill THIS slot with plane c+8 (fill lands >=234cyc after
            // the 29cyc LDS above -- no hazard).
            if (c + DEPTH < nin) {
                const float4* ga = xin + (size_t)(c + DEPTH) * HW4;
                asm volatile("cp.async.cg.shared.global [%0], [%1], 16;\n"
                             :: "r"(sa), "l"(ga));
            }
            asm volatile("cp.async.commit_group;\n" ::: "memory");

            const float4 w0 = sDW[c * 2];       // k = 0..3
            const float4 w1 = sDW[c * 2 + 1];   // k = 4..7
            const float  bb = sB[c];

            // k=7 completes output c-7 (acc slot (u+1)&7), then emit.
            {
                const int s = (u + 1) & 7;
                acc[s].x = fmaf(w1.w, xv.x, acc[s].x);
                acc[s].y = fmaf(w1.w, xv.y, acc[s].y);
                acc[s].z = fmaf(w1.w, xv.z, acc[s].z);
                acc[s].w = fmaf(w1.w, xv.w, acc[s].w);
                if ((unsigned)(c - 7) < (unsigned)nout)
                    __stcs(op + (size_t)c * HW4, acc[s]);
            }
            // k = 6..1 (weights zero outside valid range -> no guards).
            {
                const int s = (u + 2) & 7;
                acc[s].x = fmaf(w1.z, xv.x, acc[s].x);
                acc[s].y = fmaf(w1.z, xv.y, acc[s].y);
                acc[s].z = fmaf(w1.z, xv.z, acc[s].z);
                acc[s].w = fmaf(w1.z, xv.w, acc[s].w);
            }
            {
                const int s = (u + 3) & 7;
                acc[s].x = fmaf(w1.y, xv.x, acc[s].x);
                acc[s].y = fmaf(w1.y, xv.y, acc[s].y);
                acc[s].z = fmaf(w1.y, xv.z, acc[s].z);
                acc[s].w = fmaf(w1.y, xv.w, acc[s].w);
            }
            {
                const int s = (u + 4) & 7;
                acc[s].x = fmaf(w1.x, xv.x, acc[s].x);
                acc[s].y = fmaf(w1.x, xv.y, acc[s].y);
                acc[s].z = fmaf(w1.x, xv.z, acc[s].z);
                acc[s].w = fmaf(w1.x, xv.w, acc[s].w);
            }
            {
                const int s = (u + 5) & 7;
                acc[s].x = fmaf(w0.w, xv.x, acc[s].x);
                acc[s].y = fmaf(w0.w, xv.y, acc[s].y);
                acc[s].z = fmaf(w0.w, xv.z, acc[s].z);
                acc[s].w = fmaf(w0.w, xv.w, acc[s].w);
            }
            {
                const int s = (u + 6) & 7;
                acc[s].x = fmaf(w0.z, xv.x, acc[s].x);
                acc[s].y = fmaf(w0.z, xv.y, acc[s].y);
                acc[s].z = fmaf(w0.z, xv.z, acc[s].z);
                acc[s].w = fmaf(w0.z, xv.w, acc[s].w);
            }
            {
                const int s = (u + 7) & 7;
                acc[s].x = fmaf(w0.y, xv.x, acc[s].x);
                acc[s].y = fmaf(w0.y, xv.y, acc[s].y);
                acc[s].z = fmaf(w0.y, xv.z, acc[s].z);
                acc[s].w = fmaf(w0.y, xv.w, acc[s].w);
            }
            // k=0: (re)init acc slot u for output c with bias + 1st term.
            acc[u].x = fmaf(w0.x, xv.x, bb);
            acc[u].y = fmaf(w0.x, xv.y, bb);
            acc[u].z = fmaf(w0.x, xv.z, bb);
            acc[u].w = fmaf(w0.x, xv.w, bb);
        }
    }
}

extern "C" void kernel_launch(void* const* d_in, const int* in_sizes, int n_in,
                              void* d_out, int out_size) {
    const float* x  = (const float*)d_in[0];
    const float* Wg = (const float*)d_in[1];
    const float* b  = (const float*)d_in[2];
    float4* out = (float4*)d_out;

    dim3 grid(65536 / BLK, NCHUNK);
    neigh_conv_kernel<<<grid, BLK>>>(x, Wg, b, out);
}